// round 17
// baseline (speedup 1.0000x reference)
#include <cuda_runtime.h>

// ContinuousCRF, fused persistent kernel, tag-in-data wavefront sync with
// UNIFORM tagged init: each CTA softmaxes only its own row and publishes q0
// through the same relaxed single-copy-atomic 16B path used by iterations
// 1..4 (tags base+1..base+5, anchor = buffer0's last tag). Flat 960-cell
// halo mapping across all 12 warps; first poll samples for the next
// iteration issued BEFORE the epilogue to hide one L2 round trip.
// 96 CTAs (one row each), 384 threads = 4 lanes/pixel, 20 register-hoisted
// disk taps per lane, shfl_xor reduction, 1 __syncthreads per iteration.

#define HH 96
#define WW 96
#define NPIX (HH * WW)
#define HALO 5
#define TW (WW + 2 * HALO)     // 106 smem cols
#define SROWS (1 + 2 * HALO)   // 11 smem rows
#define NBLK HH
#define TPB 384
#define NITER 5
#define TPG 20                 // taps per group (80 / 4)
#define NHCELL (2 * HALO * WW) // 960 halo cells

__device__ float4 g_q[2][NPIX];   // payload (q0,q1,q2) + tag in .w

// ---- relaxed 128-bit accesses (single-copy atomic, scope gpu) ----
__device__ __forceinline__ float4 ld_rlx_f4(const float4* p)
{
    float4 v;
    asm volatile("{\n\t"
                 ".reg .b128 rr;\n\t"
                 "ld.relaxed.gpu.global.b128 rr, [%4];\n\t"
                 "mov.b128 {%0, %1, %2, %3}, rr;\n\t"
                 "}"
                 : "=f"(v.x), "=f"(v.y), "=f"(v.z), "=f"(v.w) : "l"(p));
    return v;
}
__device__ __forceinline__ void st_rlx_f4(float4* p, float4 v)
{
    asm volatile("{\n\t"
                 ".reg .b128 rr;\n\t"
                 "mov.b128 rr, {%1, %2, %3, %4};\n\t"
                 "st.relaxed.gpu.global.b128 [%0], rr;\n\t"
                 "}"
                 :: "l"(p), "f"(v.x), "f"(v.y), "f"(v.z), "f"(v.w) : "memory");
}

// Hoist taps [G*20, G*20+20) of the 80 valid (dy,dx) disk offsets into
// registers (compile-time indices -> no local-memory spill).
template <int G>
__device__ __forceinline__ void fill_taps(int* off, float* wt)
{
    int t = 0, c = 0;
#pragma unroll
    for (int dy = -5; dy <= 5; dy++) {
#pragma unroll
        for (int dx = -5; dx <= 5; dx++) {
            const int d2 = dy * dy + dx * dx;
            if (d2 == 0 || d2 > 25) continue;
            if (t >= G * TPG && t < (G + 1) * TPG) {
                off[c] = dy * TW + dx;
                wt[c]  = expf(-sqrtf((float)d2));
                c++;
            }
            t++;
        }
    }
}

__global__ __launch_bounds__(TPB, 1)
void crf_all(const float* __restrict__ unary,
             const float* __restrict__ comp,
             float* __restrict__ out)
{
    __shared__ float4 s_q[2][SROWS * TW];   // double-buffered padded tile

    const int tid = threadIdx.x;
    const int y   = blockIdx.x;
    const int sub = tid & 3;           // tap quarter (4 adjacent lanes/pixel)
    const int px  = tid >> 2;          // 0..95
    const int n   = y * WW + px;

    // Monotonic tag base. Buffer 0's last write of the previous replay is
    // q4 with tag base_prev + 5 = new base. Zero-init -> 0 on first run.
    const float base = ld_rlx_f4(&g_q[0][y * WW]).w;

    // Tap set for this lane, in registers (divergent once, init only).
    int off[TPG]; float wt[TPG];
    switch (sub) {
        case 0:  fill_taps<0>(off, wt); break;
        case 1:  fill_taps<1>(off, wt); break;
        case 2:  fill_taps<2>(off, wt); break;
        default: fill_taps<3>(off, wt); break;
    }

    const float c00 = __ldg(comp + 0), c01 = __ldg(comp + 1), c02 = __ldg(comp + 2);
    const float c10 = __ldg(comp + 3), c11 = __ldg(comp + 4), c12 = __ldg(comp + 5);
    const float c20 = __ldg(comp + 6), c21 = __ldg(comp + 7), c22 = __ldg(comp + 8);

    // Own pixel's unary logits (registers, all iterations).
    const float u0 = __ldg(unary + n);
    const float u1 = __ldg(unary + NPIX + n);
    const float u2 = __ldg(unary + 2 * NPIX + n);

    // Flat halo mapping: 960 cells (10 rows x 96 px) over 384 threads,
    // cells tid, tid+384, tid+768. Precompute global/tile offsets.
    int goff[3], toff[3];
#pragma unroll
    for (int k = 0; k < 3; k++) {
        goff[k] = -1; toff[k] = 0;
        const int cell = tid + k * TPB;
        if (cell < NHCELL) {
            const int r   = cell / WW;            // 0..9
            const int x   = cell - r * WW;
            const int hrr = (r < HALO) ? r : r + 1;   // skip own row
            const int gy  = y - HALO + hrr;
            if (gy >= 0 && gy < HH) {
                goff[k] = gy * WW + x;
                toff[k] = hrr * TW + HALO + x;
            }
        }
    }
    const bool m0 = goff[0] >= 0, m1 = goff[1] >= 0, m2 = goff[2] >= 0;

    // Zero the pad cells of BOTH tiles (never touched again).
    for (int i = tid; i < SROWS * TW; i += TPB) {
        const int r  = i / TW;
        const int cc = i - r * TW;
        const int gy = y - HALO + r;
        const int gx = cc - HALO;
        if (!(gy >= 0 && gy < HH && gx >= 0 && gx < WW)) {
            s_q[0][i] = make_float4(0.f, 0.f, 0.f, 0.f);
            s_q[1][i] = make_float4(0.f, 0.f, 0.f, 0.f);
        }
    }

    const int center = HALO * TW + HALO + px;

    // All threads must read the anchor before the publisher overwrites it.
    __syncthreads();

    // ---- init: own row only. q0 = softmax(unary), publish tag base+1. ----
    {
        const float mx = fmaxf(u0, fmaxf(u1, u2));
        const float e0 = expf(u0 - mx), e1 = expf(u1 - mx), e2 = expf(u2 - mx);
        const float rs = 1.f / (e0 + e1 + e2);
        if (sub == 0) {
            st_rlx_f4(&g_q[0][n], make_float4(e0 * rs, e1 * rs, e2 * rs, base + 1.f));
            s_q[0][center] = make_float4(e0 * rs, e1 * rs, e2 * rs, 0.f);
        }
    }

    // Pre-issue first halo samples for s=0 (publish already issued above).
    float4 v0, v1, v2;
    {
        const float4* __restrict__ src = g_q[0];
        if (m0) v0 = ld_rlx_f4(src + goff[0]);
        if (m1) v1 = ld_rlx_f4(src + goff[1]);
        if (m2) v2 = ld_rlx_f4(src + goff[2]);
    }

    for (int s = 0; s < NITER; s++) {
        const float tag = base + (float)(s + 1);      // tag of q_s
        const float4* __restrict__ src  = g_q[s & 1];
        float4*       __restrict__ tile = s_q[s & 1];

        // ---- complete halo: reload only stale cells ----
        while ((m0 && v0.w != tag) || (m1 && v1.w != tag) || (m2 && v2.w != tag)) {
            if (m0 && v0.w != tag) v0 = ld_rlx_f4(src + goff[0]);
            if (m1 && v1.w != tag) v1 = ld_rlx_f4(src + goff[1]);
            if (m2 && v2.w != tag) v2 = ld_rlx_f4(src + goff[2]);
        }
        if (m0) tile[toff[0]] = v0;
        if (m1) tile[toff[1]] = v1;
        if (m2) tile[toff[2]] = v2;
        __syncthreads();   // (A) tile complete before stencil reads

        // ---- 20-tap quarter stencil, uniform across the warp ----
        float a0 = 0.f, a1 = 0.f, a2 = 0.f;
#pragma unroll
        for (int k = 0; k < TPG; k++) {
            const float4 v = tile[center + off[k]];
            a0 = fmaf(wt[k], v.x, a0);
            a1 = fmaf(wt[k], v.y, a1);
            a2 = fmaf(wt[k], v.z, a2);
        }

        // Pre-issue next iteration's halo samples (overlaps the epilogue;
        // almost certainly stale -> spin at next loop top revalidates).
        if (s + 1 < NITER) {
            const float4* __restrict__ nsrc = g_q[(s + 1) & 1];
            if (m0) v0 = ld_rlx_f4(nsrc + goff[0]);
            if (m1) v1 = ld_rlx_f4(nsrc + goff[1]);
            if (m2) v2 = ld_rlx_f4(nsrc + goff[2]);
        }

        // reduce across the 4 sub-lanes of this pixel
        a0 += __shfl_xor_sync(0xffffffffu, a0, 1);
        a0 += __shfl_xor_sync(0xffffffffu, a0, 2);
        a1 += __shfl_xor_sync(0xffffffffu, a1, 1);
        a1 += __shfl_xor_sync(0xffffffffu, a1, 2);
        a2 += __shfl_xor_sync(0xffffffffu, a2, 1);
        a2 += __shfl_xor_sync(0xffffffffu, a2, 2);

        // compat mix + softmax (redundant on the 4 lanes; cheap)
        const float cm0 = c00 * a0 + c01 * a1 + c02 * a2;
        const float cm1 = c10 * a0 + c11 * a1 + c12 * a2;
        const float cm2 = c20 * a0 + c21 * a1 + c22 * a2;
        const float l0 = u0 + cm0, l1 = u1 + cm1, l2 = u2 + cm2;
        const float mx = fmaxf(l0, fmaxf(l1, l2));
        float e0 = expf(l0 - mx), e1 = expf(l1 - mx), e2 = expf(l2 - mx);
        const float rs = 1.f / (e0 + e1 + e2);
        e0 *= rs; e1 *= rs; e2 *= rs;

        if (s == NITER - 1) {
            // channel-parallel final store (one plane per sub-lane)
            if (sub == 0)      out[n]            = e0;
            else if (sub == 1) out[NPIX + n]     = e1;
            else if (sub == 2) out[2 * NPIX + n] = e2;
        } else {
            if (sub == 0) {
                // Publish q_{s+1}: ONE atomic 16B store (tag base+s+2).
                st_rlx_f4(&g_q[(s + 1) & 1][n],
                          make_float4(e0, e1, e2, base + (float)(s + 2)));
                // Own row straight into the next tile (ordered by next bar A).
                s_q[(s + 1) & 1][center] = make_float4(e0, e1, e2, 0.f);
            }
        }
    }
}

extern "C" void kernel_launch(void* const* d_in, const int* in_sizes, int n_in,
                              void* d_out, int out_size)
{
    (void)in_sizes; (void)n_in; (void)out_size;
    const float* unary = (const float*)d_in[0];
    const float* comp  = (const float*)d_in[1];
    float* out = (float*)d_out;

    crf_all<<<NBLK, TPB>>>(unary, comp, out);
}